// round 1
// baseline (speedup 1.0000x reference)
#include <cuda_runtime.h>
#include <cuda_bf16.h>
#include <math.h>

// Problem constants (fixed by the dataset)
#define NN   100000
#define EE   3200000
#define HIGH 384
#define LOW  64
#define EMB  128
#define HID  128
#define OUTD 2

// ---------------------------------------------------------------------------
// Device scratch (allocation-free rule: static __device__ arrays)
// ---------------------------------------------------------------------------
__device__ int   g_cnt[NN];
__device__ float g_dis[NN];
__device__ int   g_off[NN + 1];
__device__ int   g_cursor[NN];
__device__ int   g_adj_src[EE];
__device__ float g_adj_w[EE];
__device__ int   g_partial[128];
__device__ int   g_prefix[128];
__device__ float g_emb [NN * 128];
__device__ float g_bufA[NN * 128];   // xl (pre-aggregation) buffer
__device__ float g_bufB[NN * 128];   // h  (post-aggregation) buffer

static const int SCAN_B = 1024;
static const int NSCB   = (NN + SCAN_B - 1) / SCAN_B;   // 98

// ---------------------------------------------------------------------------
// Preprocessing: degree histogram, dis = rsqrt(deg+1), CSR build
// ---------------------------------------------------------------------------
__global__ void k_zero_cnt() {
    int i = blockIdx.x * blockDim.x + threadIdx.x;
    if (i < NN) g_cnt[i] = 0;
}

__global__ void k_hist(const int* __restrict__ dst) {
    int e = blockIdx.x * blockDim.x + threadIdx.x;
    if (e < EE) atomicAdd(&g_cnt[dst[e]], 1);
}

__global__ void k_dis() {
    int i = blockIdx.x * blockDim.x + threadIdx.x;
    if (i < NN) g_dis[i] = rsqrtf((float)g_cnt[i] + 1.0f);
}

__global__ void k_scan_partial() {
    __shared__ int s[SCAN_B];
    int t = threadIdx.x;
    int i = blockIdx.x * SCAN_B + t;
    s[t] = (i < NN) ? g_cnt[i] : 0;
    __syncthreads();
    for (int d = SCAN_B / 2; d > 0; d >>= 1) {
        if (t < d) s[t] += s[t + d];
        __syncthreads();
    }
    if (t == 0) g_partial[blockIdx.x] = s[0];
}

__global__ void k_scan_top() {
    int a = 0;
    for (int b = 0; b < NSCB; b++) { g_prefix[b] = a; a += g_partial[b]; }
}

__global__ void k_scan_final() {
    __shared__ int s[SCAN_B];
    int t = threadIdx.x;
    int i = blockIdx.x * SCAN_B + t;
    int v = (i < NN) ? g_cnt[i] : 0;
    s[t] = v;
    __syncthreads();
    for (int d = 1; d < SCAN_B; d <<= 1) {
        int x = (t >= d) ? s[t - d] : 0;
        __syncthreads();
        s[t] += x;
        __syncthreads();
    }
    if (i < NN) {
        int excl = g_prefix[blockIdx.x] + s[t] - v;
        g_off[i]    = excl;
        g_cursor[i] = excl;
        if (i == NN - 1) g_off[NN] = g_prefix[blockIdx.x] + s[t];
    }
}

__global__ void k_scatter(const int* __restrict__ src, const int* __restrict__ dst) {
    int e = blockIdx.x * blockDim.x + threadIdx.x;
    if (e < EE) {
        int d = dst[e], s = src[e];
        int pos = atomicAdd(&g_cursor[d], 1);
        g_adj_src[pos] = s;
        g_adj_w[pos]   = g_dis[s] * g_dis[d];
    }
}

// ---------------------------------------------------------------------------
// SGEMM: C[M x 128] = A[M x K] @ B[K x 128]   (optional ACC/BIAS/RELU)
// 128x128 tile, 256 threads, 8x8 per-thread micro-tile, K-tile = 8
// ---------------------------------------------------------------------------
template <bool ACC, bool BIAS, bool RELU>
__global__ void __launch_bounds__(256)
k_sgemm128(const float* __restrict__ A, int lda, int M, int K,
           const float* __restrict__ B,
           const float* __restrict__ bias,
           float* __restrict__ C)
{
    __shared__ float As[8][132];
    __shared__ float Bs[8][132];

    int tid = threadIdx.x;
    int tx = tid & 15, ty = tid >> 4;
    int row0 = blockIdx.x * 128;

    int ar = tid >> 1, aq = tid & 1;          // A loader: 2 float4 per row of 8 Ks
    int bk = tid >> 5, bc = (tid & 31) * 4;   // B loader

    float acc[8][8];
#pragma unroll
    for (int i = 0; i < 8; i++)
#pragma unroll
        for (int j = 0; j < 8; j++) acc[i][j] = 0.0f;

    int nk = K / 8;
    for (int kt = 0; kt < nk; kt++) {
        int arow = row0 + ar;
        float4 av = make_float4(0.f, 0.f, 0.f, 0.f);
        if (arow < M)
            av = *(const float4*)&A[(size_t)arow * lda + kt * 8 + aq * 4];
        As[aq * 4 + 0][ar] = av.x;
        As[aq * 4 + 1][ar] = av.y;
        As[aq * 4 + 2][ar] = av.z;
        As[aq * 4 + 3][ar] = av.w;

        float4 bv = *(const float4*)&B[(size_t)(kt * 8 + bk) * 128 + bc];
        *(float4*)&Bs[bk][bc] = bv;

        __syncthreads();
#pragma unroll
        for (int k = 0; k < 8; k++) {
            float a[8], b[8];
            *(float4*)&a[0] = *(const float4*)&As[k][ty * 8];
            *(float4*)&a[4] = *(const float4*)&As[k][ty * 8 + 4];
            *(float4*)&b[0] = *(const float4*)&Bs[k][tx * 8];
            *(float4*)&b[4] = *(const float4*)&Bs[k][tx * 8 + 4];
#pragma unroll
            for (int i = 0; i < 8; i++)
#pragma unroll
                for (int j = 0; j < 8; j++)
                    acc[i][j] = fmaf(a[i], b[j], acc[i][j]);
        }
        __syncthreads();
    }

#pragma unroll
    for (int i = 0; i < 8; i++) {
        int row = row0 + ty * 8 + i;
        if (row >= M) continue;
#pragma unroll
        for (int jj = 0; jj < 8; jj += 4) {
            int col = tx * 8 + jj;
            float4 c = make_float4(acc[i][jj], acc[i][jj + 1], acc[i][jj + 2], acc[i][jj + 3]);
            if (BIAS) {
                float4 bb = *(const float4*)&bias[col];
                c.x += bb.x; c.y += bb.y; c.z += bb.z; c.w += bb.w;
            }
            if (ACC) {
                float4 o = *(const float4*)&C[(size_t)row * 128 + col];
                c.x += o.x; c.y += o.y; c.z += o.z; c.w += o.w;
            }
            if (RELU) {
                c.x = fmaxf(c.x, 0.f); c.y = fmaxf(c.y, 0.f);
                c.z = fmaxf(c.z, 0.f); c.w = fmaxf(c.w, 0.f);
            }
            *(float4*)&C[(size_t)row * 128 + col] = c;
        }
    }
}

// ---------------------------------------------------------------------------
// Pull-mode GCN aggregation: one warp per destination node.
// h[v] = relu( bias + dis[v]^2 * xl[v] + sum_{e: dst=v} w_e * xl[src_e] )
// ---------------------------------------------------------------------------
__global__ void __launch_bounds__(256)
k_agg(const float* __restrict__ xl, const float* __restrict__ bias,
      float* __restrict__ h)
{
    int warp = (blockIdx.x * blockDim.x + threadIdx.x) >> 5;
    int lane = threadIdx.x & 31;
    if (warp >= NN) return;
    int v = warp;
    int c = lane * 4;

    float dv = g_dis[v];
    float4 x = *(const float4*)&xl[(size_t)v * 128 + c];
    float sl = dv * dv;
    float4 acc  = make_float4(x.x * sl, x.y * sl, x.z * sl, x.w * sl);
    float4 acc2 = make_float4(0.f, 0.f, 0.f, 0.f);

    int beg = g_off[v], end = g_off[v + 1];
    int i = beg;
    for (; i + 1 < end; i += 2) {
        int   s0 = g_adj_src[i];
        int   s1 = g_adj_src[i + 1];
        float w0 = g_adj_w[i];
        float w1 = g_adj_w[i + 1];
        float4 a = *(const float4*)&xl[(size_t)s0 * 128 + c];
        float4 b = *(const float4*)&xl[(size_t)s1 * 128 + c];
        acc.x  = fmaf(a.x, w0, acc.x);  acc.y  = fmaf(a.y, w0, acc.y);
        acc.z  = fmaf(a.z, w0, acc.z);  acc.w  = fmaf(a.w, w0, acc.w);
        acc2.x = fmaf(b.x, w1, acc2.x); acc2.y = fmaf(b.y, w1, acc2.y);
        acc2.z = fmaf(b.z, w1, acc2.z); acc2.w = fmaf(b.w, w1, acc2.w);
    }
    if (i < end) {
        int s0 = g_adj_src[i]; float w0 = g_adj_w[i];
        float4 a = *(const float4*)&xl[(size_t)s0 * 128 + c];
        acc.x = fmaf(a.x, w0, acc.x); acc.y = fmaf(a.y, w0, acc.y);
        acc.z = fmaf(a.z, w0, acc.z); acc.w = fmaf(a.w, w0, acc.w);
    }
    acc.x += acc2.x; acc.y += acc2.y; acc.z += acc2.z; acc.w += acc2.w;

    float4 b = *(const float4*)&bias[c];
    acc.x = fmaxf(acc.x + b.x, 0.f);
    acc.y = fmaxf(acc.y + b.y, 0.f);
    acc.z = fmaxf(acc.z + b.z, 0.f);
    acc.w = fmaxf(acc.w + b.w, 0.f);
    *(float4*)&h[(size_t)v * 128 + c] = acc;
}

// ---------------------------------------------------------------------------
// Head: out = log_softmax(h @ W_lin + b_lin), OUT=2. One warp per node.
// ---------------------------------------------------------------------------
__global__ void __launch_bounds__(256)
k_head(const float* __restrict__ h, const float* __restrict__ Wl,
       const float* __restrict__ bl, float* __restrict__ out)
{
    int warp = (blockIdx.x * blockDim.x + threadIdx.x) >> 5;
    int lane = threadIdx.x & 31;
    if (warp >= NN) return;
    int v = warp;
    int c = lane * 4;

    float4 x = *(const float4*)&h[(size_t)v * 128 + c];
    float p0 = x.x * Wl[(c + 0) * 2 + 0] + x.y * Wl[(c + 1) * 2 + 0]
             + x.z * Wl[(c + 2) * 2 + 0] + x.w * Wl[(c + 3) * 2 + 0];
    float p1 = x.x * Wl[(c + 0) * 2 + 1] + x.y * Wl[(c + 1) * 2 + 1]
             + x.z * Wl[(c + 2) * 2 + 1] + x.w * Wl[(c + 3) * 2 + 1];
#pragma unroll
    for (int off = 16; off > 0; off >>= 1) {
        p0 += __shfl_down_sync(0xFFFFFFFF, p0, off);
        p1 += __shfl_down_sync(0xFFFFFFFF, p1, off);
    }
    if (lane == 0) {
        float z0 = p0 + bl[0];
        float z1 = p1 + bl[1];
        float m  = fmaxf(z0, z1);
        float lse = m + logf(expf(z0 - m) + expf(z1 - m));
        out[v * 2 + 0] = z0 - lse;
        out[v * 2 + 1] = z1 - lse;
    }
}

// ---------------------------------------------------------------------------
// Launch
// ---------------------------------------------------------------------------
extern "C" void kernel_launch(void* const* d_in, const int* in_sizes, int n_in,
                              void* d_out, int out_size)
{
    const float* high  = (const float*)d_in[0];
    const float* low   = (const float*)d_in[1];
    const int*   eidx  = (const int*)  d_in[2];
    const float* W_emb = (const float*)d_in[3];
    const float* b_emb = (const float*)d_in[4];
    const float* W1    = (const float*)d_in[5];
    const float* b1    = (const float*)d_in[6];
    const float* W2    = (const float*)d_in[7];
    const float* b2    = (const float*)d_in[8];
    const float* W_lin = (const float*)d_in[9];
    const float* b_lin = (const float*)d_in[10];
    float* out = (float*)d_out;

    const int* src = eidx;
    const int* dst = eidx + EE;

    float* emb;  cudaGetSymbolAddress((void**)&emb,  g_emb);
    float* bufA; cudaGetSymbolAddress((void**)&bufA, g_bufA);
    float* bufB; cudaGetSymbolAddress((void**)&bufB, g_bufB);

    const int TB = 256;
    int nblkN = (NN + TB - 1) / TB;
    int nblkE = (EE + TB - 1) / TB;
    int gemm_blk = (NN + 127) / 128;
    int warp_blk = (NN + (TB / 32) - 1) / (TB / 32);

    // ---- preprocessing: degrees + CSR ----
    k_zero_cnt<<<nblkN, TB>>>();
    k_hist<<<nblkE, TB>>>(dst);
    k_dis<<<nblkN, TB>>>();
    k_scan_partial<<<NSCB, SCAN_B>>>();
    k_scan_top<<<1, 1>>>();
    k_scan_final<<<NSCB, SCAN_B>>>();
    k_scatter<<<nblkE, TB>>>(src, dst);

    // ---- low embedding: emb = relu(low @ W_emb + b_emb) ----
    k_sgemm128<false, true, true><<<gemm_blk, 256>>>(low, LOW, NN, LOW, W_emb, b_emb, emb);

    // ---- layer 1: xl = [high | emb] @ W1 ----
    k_sgemm128<false, false, false><<<gemm_blk, 256>>>(high, HIGH, NN, HIGH, W1, nullptr, bufA);
    k_sgemm128<true,  false, false><<<gemm_blk, 256>>>(emb, EMB, NN, EMB, W1 + (size_t)HIGH * 128, nullptr, bufA);
    k_agg<<<warp_blk, TB>>>(bufA, b1, bufB);

    // ---- layer 2: xl = h1 @ W2 ----
    k_sgemm128<false, false, false><<<gemm_blk, 256>>>(bufB, HID, NN, HID, W2, nullptr, bufA);
    k_agg<<<warp_blk, TB>>>(bufA, b2, bufB);

    // ---- head ----
    k_head<<<warp_blk, TB>>>(bufB, W_lin, b_lin, out);

    (void)in_sizes; (void)n_in; (void)out_size;
}

// round 4
// speedup vs baseline: 1.2781x; 1.2781x over previous
#include <cuda_runtime.h>
#include <cuda_bf16.h>
#include <cstdint>
#include <math.h>

// Problem constants (fixed by the dataset)
#define NN   100000
#define EE   3200000
#define HIGH 384
#define LOW  64
#define EMB  128
#define HID  128
#define OUTD 2

// ---------------------------------------------------------------------------
// Device scratch (allocation-free rule: static __device__ arrays)
// ---------------------------------------------------------------------------
__device__ int   g_cnt[NN];
__device__ float g_dis[NN];
__device__ int   g_off[NN + 1];
__device__ int   g_cursor[NN];
__device__ int   g_adj_src[EE];
__device__ float g_adj_w[EE];
__device__ int   g_partial[128];
__device__ int   g_prefix[128];
__device__ float g_emb [NN * 128];
__device__ float g_bufA[NN * 128];   // xl (pre-aggregation) buffer
__device__ float g_bufB[NN * 128];   // h  (post-aggregation) buffer

// bf16 hi/lo split weights, col-major [n][k] (n = out feature 0..127)
__device__ __nv_bfloat16 g_W1hi[512 * 128], g_W1lo[512 * 128];
__device__ __nv_bfloat16 g_W2hi[128 * 128], g_W2lo[128 * 128];
__device__ __nv_bfloat16 g_Wehi[64 * 128],  g_Welo[64 * 128];

static const int SCAN_B = 1024;
static const int NSCB   = (NN + SCAN_B - 1) / SCAN_B;   // 98

// ---------------------------------------------------------------------------
// Preprocessing: degree histogram, dis = rsqrt(deg+1), CSR build
// ---------------------------------------------------------------------------
__global__ void k_zero_cnt() {
    int i = blockIdx.x * blockDim.x + threadIdx.x;
    if (i < NN) g_cnt[i] = 0;
}

__global__ void k_hist(const int* __restrict__ dst) {
    int e = blockIdx.x * blockDim.x + threadIdx.x;
    if (e < EE) atomicAdd(&g_cnt[dst[e]], 1);
}

__global__ void k_dis() {
    int i = blockIdx.x * blockDim.x + threadIdx.x;
    if (i < NN) g_dis[i] = rsqrtf((float)g_cnt[i] + 1.0f);
}

__global__ void k_scan_partial() {
    __shared__ int s[SCAN_B];
    int t = threadIdx.x;
    int i = blockIdx.x * SCAN_B + t;
    s[t] = (i < NN) ? g_cnt[i] : 0;
    __syncthreads();
    for (int d = SCAN_B / 2; d > 0; d >>= 1) {
        if (t < d) s[t] += s[t + d];
        __syncthreads();
    }
    if (t == 0) g_partial[blockIdx.x] = s[0];
}

__global__ void k_scan_top() {
    int a = 0;
    for (int b = 0; b < NSCB; b++) { g_prefix[b] = a; a += g_partial[b]; }
}

__global__ void k_scan_final() {
    __shared__ int s[SCAN_B];
    int t = threadIdx.x;
    int i = blockIdx.x * SCAN_B + t;
    int v = (i < NN) ? g_cnt[i] : 0;
    s[t] = v;
    __syncthreads();
    for (int d = 1; d < SCAN_B; d <<= 1) {
        int x = (t >= d) ? s[t - d] : 0;
        __syncthreads();
        s[t] += x;
        __syncthreads();
    }
    if (i < NN) {
        int excl = g_prefix[blockIdx.x] + s[t] - v;
        g_off[i]    = excl;
        g_cursor[i] = excl;
        if (i == NN - 1) g_off[NN] = g_prefix[blockIdx.x] + s[t];
    }
}

__global__ void k_scatter(const int* __restrict__ src, const int* __restrict__ dst) {
    int e = blockIdx.x * blockDim.x + threadIdx.x;
    if (e < EE) {
        int d = dst[e], s = src[e];
        int pos = atomicAdd(&g_cursor[d], 1);
        g_adj_src[pos] = s;
        g_adj_w[pos]   = g_dis[s] * g_dis[d];
    }
}

// ---------------------------------------------------------------------------
// Weight prep: fp32 row-major [K][128] -> bf16 hi/lo col-major [128][K]
// ---------------------------------------------------------------------------
__global__ void k_prep_w(const float* __restrict__ W, int K,
                         __nv_bfloat16* __restrict__ hi,
                         __nv_bfloat16* __restrict__ lo)
{
    int idx = blockIdx.x * blockDim.x + threadIdx.x;
    if (idx >= K * 128) return;
    int k = idx >> 7, n = idx & 127;
    float f = W[idx];
    __nv_bfloat16 h = __float2bfloat16_rn(f);
    float r = f - __bfloat162float(h);
    hi[n * K + k] = h;
    lo[n * K + k] = __float2bfloat16_rn(r);
}

// ---------------------------------------------------------------------------
// Tensor-core GEMM: C[M x 128] = A[M x K] @ B[K x 128] via bf16x3 split HMMA
// Block 128x128, 256 threads (8 warps as 4x2, warp tile 32x64), k-step 16.
// A: fp32 global, split to bf16 hi/lo in-kernel. B: pre-split bf16 col-major.
// ---------------------------------------------------------------------------
#define MMA_BF16(C, A, B0, B1) \
    asm volatile("mma.sync.aligned.m16n8k16.row.col.f32.bf16.bf16.f32 " \
        "{%0,%1,%2,%3}, {%4,%5,%6,%7}, {%8,%9}, {%0,%1,%2,%3};" \
        : "+f"(C[0]), "+f"(C[1]), "+f"(C[2]), "+f"(C[3]) \
        : "r"(A[0]), "r"(A[1]), "r"(A[2]), "r"(A[3]), "r"(B0), "r"(B1))

#define LDSM_X4(D, ADDR) \
    asm volatile("ldmatrix.sync.aligned.m8n8.x4.shared.b16 {%0,%1,%2,%3}, [%4];" \
        : "=r"(D[0]), "=r"(D[1]), "=r"(D[2]), "=r"(D[3]) : "r"(ADDR))

template <bool ACC, bool BIAS, bool RELU>
__global__ void __launch_bounds__(256)
k_hgemm(const float* __restrict__ A, int lda, int M, int Kt,
        const __nv_bfloat16* __restrict__ Bhi, const __nv_bfloat16* __restrict__ Blo,
        int ldb, int kbase,
        const float* __restrict__ bias, float* __restrict__ C)
{
    // stride 24 halves (48B): ldmatrix rows 16B aligned + conflict-free
    __shared__ __align__(16) __nv_bfloat16 sAh[128 * 24];
    __shared__ __align__(16) __nv_bfloat16 sAl[128 * 24];
    __shared__ __align__(16) __nv_bfloat16 sBh[128 * 24];
    __shared__ __align__(16) __nv_bfloat16 sBl[128 * 24];

    const int tid  = threadIdx.x;
    const int warp = tid >> 5, lane = tid & 31;
    const int wm   = warp >> 1, wn = warp & 1;      // 4 x 2 warp grid
    const int g    = lane >> 2, tq = lane & 3;
    const int row0 = blockIdx.x * 128;

    const int arow = tid >> 1, aq = tid & 1;        // loader: row/n, 8-elem half

    float acc[2][8][4];
#pragma unroll
    for (int mi = 0; mi < 2; mi++)
#pragma unroll
        for (int ni = 0; ni < 8; ni++)
#pragma unroll
            for (int q = 0; q < 4; q++) acc[mi][ni][q] = 0.0f;

    float4 pa0, pa1;
    uint4  pbh, pbl;

    // prefetch tile 0
    {
        int r = row0 + arow;
        if (r < M) {
            const float* p = A + (size_t)r * lda + aq * 8;
            pa0 = *(const float4*)p;
            pa1 = *(const float4*)(p + 4);
        } else {
            pa0 = make_float4(0.f, 0.f, 0.f, 0.f);
            pa1 = pa0;
        }
        size_t bo = (size_t)arow * ldb + kbase + aq * 8;
        pbh = *(const uint4*)(Bhi + bo);
        pbl = *(const uint4*)(Blo + bo);
    }

    for (int kt = 0; kt < Kt; kt++) {
        // ---- store prefetched tile to smem (split A on the fly) ----
        {
            uint32_t* wh = (uint32_t*)sAh;
            uint32_t* wl = (uint32_t*)sAl;
            int base = arow * 12 + aq * 4;
            float f[8] = {pa0.x, pa0.y, pa0.z, pa0.w, pa1.x, pa1.y, pa1.z, pa1.w};
#pragma unroll
            for (int j = 0; j < 4; j++) {
                __nv_bfloat162 h2, l2;
                h2.x = __float2bfloat16_rn(f[2 * j]);
                h2.y = __float2bfloat16_rn(f[2 * j + 1]);
                l2.x = __float2bfloat16_rn(f[2 * j]     - __bfloat162float(h2.x));
                l2.y = __float2bfloat16_rn(f[2 * j + 1] - __bfloat162float(h2.y));
                wh[base + j] = *(uint32_t*)&h2;
                wl[base + j] = *(uint32_t*)&l2;
            }
            *(uint4*)((char*)sBh + arow * 48 + aq * 16) = pbh;
            *(uint4*)((char*)sBl + arow * 48 + aq * 16) = pbl;
        }
        __syncthreads();

        // ---- prefetch next tile (overlaps with mma below) ----
        if (kt + 1 < Kt) {
            int r = row0 + arow;
            if (r < M) {
                const float* p = A + (size_t)r * lda + (kt + 1) * 16 + aq * 8;
                pa0 = *(const float4*)p;
                pa1 = *(const float4*)(p + 4);
            } else {
                pa0 = make_float4(0.f, 0.f, 0.f, 0.f);
                pa1 = pa0;
            }
            size_t bo = (size_t)arow * ldb + kbase + (kt + 1) * 16 + aq * 8;
            pbh = *(const uint4*)(Bhi + bo);
            pbl = *(const uint4*)(Blo + bo);
        }

        // ---- A fragments via ldmatrix ----
        uint32_t ah[2][4], al[2][4];
#pragma unroll
        for (int mi = 0; mi < 2; mi++) {
            int r = wm * 32 + mi * 16 + (lane & 15);
            int c = (lane >> 4) * 8;
            uint32_t adh = (uint32_t)__cvta_generic_to_shared(&sAh[r * 24 + c]);
            uint32_t adl = (uint32_t)__cvta_generic_to_shared(&sAl[r * 24 + c]);
            LDSM_X4(ah[mi], adh);
            LDSM_X4(al[mi], adl);
        }

        // ---- B fragments + mma ----
        const uint32_t* wbh = (const uint32_t*)sBh;
        const uint32_t* wbl = (const uint32_t*)sBl;
#pragma unroll
        for (int ni = 0; ni < 8; ni++) {
            int n = wn * 64 + ni * 8 + g;
            uint32_t b0h = wbh[n * 12 + tq];
            uint32_t b1h = wbh[n * 12 + tq + 4];
            uint32_t b0l = wbl[n * 12 + tq];
            uint32_t b1l = wbl[n * 12 + tq + 4];
#pragma unroll
            for (int mi = 0; mi < 2; mi++) {
                MMA_BF16(acc[mi][ni], ah[mi], b0h, b1h);   // hi * hi
                MMA_BF16(acc[mi][ni], al[mi], b0h, b1h);   // lo * hi
                MMA_BF16(acc[mi][ni], ah[mi], b0l, b1l);   // hi * lo
            }
        }
        __syncthreads();
    }

    // ---- epilogue ----
#pragma unroll
    for (int mi = 0; mi < 2; mi++) {
        int rbase = row0 + wm * 32 + mi * 16 + g;
#pragma unroll
        for (int ni = 0; ni < 8; ni++) {
            int col = wn * 64 + ni * 8 + tq * 2;
#pragma unroll
            for (int h = 0; h < 2; h++) {
                int row = rbase + h * 8;
                if (row < M) {
                    float v0 = acc[mi][ni][2 * h];
                    float v1 = acc[mi][ni][2 * h + 1];
                    if (BIAS) { v0 += bias[col]; v1 += bias[col + 1]; }
                    float* cp = &C[(size_t)row * 128 + col];
                    if (ACC) { v0 += cp[0]; v1 += cp[1]; }
                    if (RELU) { v0 = fmaxf(v0, 0.f); v1 = fmaxf(v1, 0.f); }
                    cp[0] = v0; cp[1] = v1;
                }
            }
        }
    }
}

// ---------------------------------------------------------------------------
// Pull-mode GCN aggregation: one warp per destination node.
// h[v] = relu( bias + dis[v]^2 * xl[v] + sum_{e: dst=v} w_e * xl[src_e] )
// ---------------------------------------------------------------------------
__global__ void __launch_bounds__(256)
k_agg(const float* __restrict__ xl, const float* __restrict__ bias,
      float* __restrict__ h)
{
    int warp = (blockIdx.x * blockDim.x + threadIdx.x) >> 5;
    int lane = threadIdx.x & 31;
    if (warp >= NN) return;
    int v = warp;
    int c = lane * 4;

    float dv = g_dis[v];
    float4 x = *(const float4*)&xl[(size_t)v * 128 + c];
    float sl = dv * dv;
    float4 acc  = make_float4(x.x * sl, x.y * sl, x.z * sl, x.w * sl);
    float4 acc2 = make_float4(0.f, 0.f, 0.f, 0.f);

    int beg = g_off[v], end = g_off[v + 1];
    int i = beg;
    for (; i + 1 < end; i += 2) {
        int   s0 = g_adj_src[i];
        int   s1 = g_adj_src[i + 1];
        float w0 = g_adj_w[i];
        float w1 = g_adj_w[i + 1];
        float4 a = *(const float4*)&xl[(size_t)s0 * 128 + c];
        float4 b = *(const float4*)&xl[(size_t)s1 * 128 + c];
        acc.x  = fmaf(a.x, w0, acc.x);  acc.y  = fmaf(a.y, w0, acc.y);
        acc.z  = fmaf(a.z, w0, acc.z);  acc.w  = fmaf(a.w, w0, acc.w);
        acc2.x = fmaf(b.x, w1, acc2.x); acc2.y = fmaf(b.y, w1, acc2.y);
        acc2.z = fmaf(b.z, w1, acc2.z); acc2.w = fmaf(b.w, w1, acc2.w);
    }
    if (i < end) {
        int s0 = g_adj_src[i]; float w0 = g_adj_w[i];
        float4 a = *(const float4*)&xl[(size_t)s0 * 128 + c];
        acc.x = fmaf(a.x, w0, acc.x); acc.y = fmaf(a.y, w0, acc.y);
        acc.z = fmaf(a.z, w0, acc.z); acc.w = fmaf(a.w, w0, acc.w);
    }
    acc.x += acc2.x; acc.y += acc2.y; acc.z += acc2.z; acc.w += acc2.w;

    float4 b = *(const float4*)&bias[c];
    acc.x = fmaxf(acc.x + b.x, 0.f);
    acc.y = fmaxf(acc.y + b.y, 0.f);
    acc.z = fmaxf(acc.z + b.z, 0.f);
    acc.w = fmaxf(acc.w + b.w, 0.f);
    *(float4*)&h[(size_t)v * 128 + c] = acc;
}

// ---------------------------------------------------------------------------
// Head: out = log_softmax(h @ W_lin + b_lin), OUT=2. One warp per node.
// ---------------------------------------------------------------------------
__global__ void __launch_bounds__(256)
k_head(const float* __restrict__ h, const float* __restrict__ Wl,
       const float* __restrict__ bl, float* __restrict__ out)
{
    int warp = (blockIdx.x * blockDim.x + threadIdx.x) >> 5;
    int lane = threadIdx.x & 31;
    if (warp >= NN) return;
    int v = warp;
    int c = lane * 4;

    float4 x = *(const float4*)&h[(size_t)v * 128 + c];
    float p0 = x.x * Wl[(c + 0) * 2 + 0] + x.y * Wl[(c + 1) * 2 + 0]
             + x.z * Wl[(c + 2) * 2 + 0] + x.w * Wl[(c + 3) * 2 + 0];
    float p1 = x.x * Wl[(c + 0) * 2 + 1] + x.y * Wl[(c + 1) * 2 + 1]
             + x.z * Wl[(c + 2) * 2 + 1] + x.w * Wl[(c + 3) * 2 + 1];
#pragma unroll
    for (int off = 16; off > 0; off >>= 1) {
        p0 += __shfl_down_sync(0xFFFFFFFF, p0, off);
        p1 += __shfl_down_sync(0xFFFFFFFF, p1, off);
    }
    if (lane == 0) {
        float z0 = p0 + bl[0];
        float z1 = p1 + bl[1];
        float m  = fmaxf(z0, z1);
        float lse = m + logf(expf(z0 - m) + expf(z1 - m));
        out[v * 2 + 0] = z0 - lse;
        out[v * 2 + 1] = z1 - lse;
    }
}

// ---------------------------------------------------------------------------
// Launch
// ---------------------------------------------------------------------------
extern "C" void kernel_launch(void* const* d_in, const int* in_sizes, int n_in,
                              void* d_out, int out_size)
{
    const float* high  = (const float*)d_in[0];
    const float* low   = (const float*)d_in[1];
    const int*   eidx  = (const int*)  d_in[2];
    const float* W_emb = (const float*)d_in[3];
    const float* b_emb = (const float*)d_in[4];
    const float* W1    = (const float*)d_in[5];
    const float* b1    = (const float*)d_in[6];
    const float* W2    = (const float*)d_in[7];
    const float* b2    = (const float*)d_in[8];
    const float* W_lin = (const float*)d_in[9];
    const float* b_lin = (const float*)d_in[10];
    float* out = (float*)d_out;

    const int* src = eidx;
    const int* dst = eidx + EE;

    float* emb;  cudaGetSymbolAddress((void**)&emb,  g_emb);
    float* bufA; cudaGetSymbolAddress((void**)&bufA, g_bufA);
    float* bufB; cudaGetSymbolAddress((void**)&bufB, g_bufB);
    __nv_bfloat16 *W1hi, *W1lo, *W2hi, *W2lo, *Wehi, *Welo;
    cudaGetSymbolAddress((void**)&W1hi, g_W1hi);
    cudaGetSymbolAddress((void**)&W1lo, g_W1lo);
    cudaGetSymbolAddress((void**)&W2hi, g_W2hi);
    cudaGetSymbolAddress((void**)&W2lo, g_W2lo);
    cudaGetSymbolAddress((void**)&Wehi, g_Wehi);
    cudaGetSymbolAddress((void**)&Welo, g_Welo);

    const int TB = 256;
    int nblkN = (NN + TB - 1) / TB;
    int nblkE = (EE + TB - 1) / TB;
    int gemm_blk = (NN + 127) / 128;
    int warp_blk = (NN + (TB / 32) - 1) / (TB / 32);

    // ---- preprocessing: degrees + CSR ----
    k_zero_cnt<<<nblkN, TB>>>();
    k_hist<<<nblkE, TB>>>(dst);
    k_dis<<<nblkN, TB>>>();
    k_scan_partial<<<NSCB, SCAN_B>>>();
    k_scan_top<<<1, 1>>>();
    k_scan_final<<<NSCB, SCAN_B>>>();
    k_scatter<<<nblkE, TB>>>(src, dst);

    // ---- weight split prep (cheap, runs every launch for determinism) ----
    k_prep_w<<<(512 * 128 + 255) / 256, 256>>>(W1,    512, W1hi, W1lo);
    k_prep_w<<<(128 * 128 + 255) / 256, 256>>>(W2,    128, W2hi, W2lo);
    k_prep_w<<<(64  * 128 + 255) / 256, 256>>>(W_emb, 64,  Wehi, Welo);

    // ---- low embedding: emb = relu(low @ W_emb + b_emb) ----
    k_hgemm<false, true, true><<<gemm_blk, 256>>>(low, LOW, NN, LOW / 16,
                                                  Wehi, Welo, LOW, 0, b_emb, emb);

    // ---- layer 1: xl = [high | emb] @ W1 ----
    k_hgemm<false, false, false><<<gemm_blk, 256>>>(high, HIGH, NN, HIGH / 16,
                                                    W1hi, W1lo, 512, 0, nullptr, bufA);
    k_hgemm<true, false, false><<<gemm_blk, 256>>>(emb, EMB, NN, EMB / 16,
                                                   W1hi, W1lo, 512, HIGH, nullptr, bufA);
    k_agg<<<warp_blk, TB>>>(bufA, b1, bufB);

    // ---- layer 2: xl = h1 @ W2 ----
    k_hgemm<false, false, false><<<gemm_blk, 256>>>(bufB, HID, NN, HID / 16,
                                                    W2hi, W2lo, 128, 0, nullptr, bufA);
    k_agg<<<warp_blk, TB>>>(bufA, b2, bufB);

    // ---- head ----
    k_head<<<warp_blk, TB>>>(bufB, W_lin, b_lin, out);

    (void)in_sizes; (void)n_in; (void)out_size;
}